// round 5
// baseline (speedup 1.0000x reference)
#include <cuda_runtime.h>
#include <math.h>

// Problem dims
#define Bb 2
#define Ss 1024
#define Hh 4544
#define NHh 71
#define HDd 64
#define H4 18176
#define Mrows 2048        // B*S
#define FRAC 4096

// ---------------- scratch (device globals: the sanctioned scratch path) ------
__device__ float g_ln [(size_t)Mrows * Hh];
__device__ float g_q  [(size_t)Mrows * Hh];
__device__ float g_k  [(size_t)Mrows * HDd];
__device__ float g_v  [(size_t)Mrows * HDd];
__device__ float g_ctx[(size_t)Mrows * Hh];
__device__ float g_att[(size_t)Mrows * Hh];
__device__ float g_mlp[(size_t)Mrows * H4];

// ---------------- LayerNorm (fractured scale/bias) ---------------------------
__global__ void ln_kernel(const float* __restrict__ x,
                          const float* __restrict__ w1, const float* __restrict__ b1,
                          const float* __restrict__ w2, const float* __restrict__ b2,
                          float* __restrict__ out)
{
    int row = blockIdx.x;
    const float4* xr = (const float4*)(x + (size_t)row * Hh);
    float s = 0.f, sq = 0.f;
    for (int i = threadIdx.x; i < Hh / 4; i += blockDim.x) {
        float4 v = xr[i];
        s  += v.x + v.y + v.z + v.w;
        sq += v.x*v.x + v.y*v.y + v.z*v.z + v.w*v.w;
    }
    #pragma unroll
    for (int o = 16; o; o >>= 1) {
        s  += __shfl_xor_sync(0xffffffffu, s,  o);
        sq += __shfl_xor_sync(0xffffffffu, sq, o);
    }
    __shared__ float rs[8], rq[8], stats[2];
    int w = threadIdx.x >> 5;
    if ((threadIdx.x & 31) == 0) { rs[w] = s; rq[w] = sq; }
    __syncthreads();
    if (threadIdx.x == 0) {
        float ts = 0.f, tq = 0.f;
        #pragma unroll
        for (int i = 0; i < 8; i++) { ts += rs[i]; tq += rq[i]; }
        float mean = ts / (float)Hh;
        float var  = tq / (float)Hh - mean * mean;
        stats[0] = mean;
        stats[1] = rsqrtf(var + 1e-5f);
    }
    __syncthreads();
    float mean = stats[0], rstd = stats[1];
    float4* orow = (float4*)(out + (size_t)row * Hh);
    for (int i = threadIdx.x; i < Hh / 4; i += blockDim.x) {
        float4 v = xr[i];
        int c = i * 4;
        float vv[4] = {v.x, v.y, v.z, v.w};
        float ov[4];
        #pragma unroll
        for (int j = 0; j < 4; j++) {
            int cc = c + j;
            float ww, bb;
            if (cc < FRAC) { ww = w1[cc];        bb = b1[cc]; }
            else           { ww = w2[cc - FRAC]; bb = b2[cc - FRAC]; }
            ov[j] = (vv[j] - mean) * rstd * ww + bb;
        }
        float4 o = {ov[0], ov[1], ov[2], ov[3]};
        orow[i] = o;
    }
}

// ---------------- NT GEMM: C[M,N] = A[M,K] * B[N,K]^T ------------------------
// BM=128, BN=64, BK=16, 256 threads, 8x4 per-thread tile.
constexpr int BM = 128, BN = 64, BK = 16;

#define GEMM_STORE_SMEM() do {                                              \
    As[akq+0][ar0]    = pa0.x; As[akq+1][ar0]    = pa0.y;                   \
    As[akq+2][ar0]    = pa0.z; As[akq+3][ar0]    = pa0.w;                   \
    As[akq+0][ar0+64] = pa1.x; As[akq+1][ar0+64] = pa1.y;                   \
    As[akq+2][ar0+64] = pa1.z; As[akq+3][ar0+64] = pa1.w;                   \
    Bs[akq+0][ar0]    = pb.x;  Bs[akq+1][ar0]    = pb.y;                    \
    Bs[akq+2][ar0]    = pb.z;  Bs[akq+3][ar0]    = pb.w;                    \
} while (0)

// EPI: 0 = plain, 1 = exact gelu, 2 = C + add1 + add2
template <int EPI>
__global__ void __launch_bounds__(256, 3) gemm_nt(
    const float* __restrict__ A, const float* __restrict__ Bw,
    float* __restrict__ C, int M, int N, int K,
    const float* __restrict__ add1, const float* __restrict__ add2)
{
    __shared__ float As[BK][BM + 4];
    __shared__ float Bs[BK][BN + 4];

    const int tid = threadIdx.x;
    const int m0 = blockIdx.y * BM, n0 = blockIdx.x * BN;
    const int ty = tid >> 4, tx = tid & 15;
    const int ar0 = tid >> 2;          // 0..63
    const int akq = (tid & 3) * 4;     // 0,4,8,12

    const float* aptr  = A  + (size_t)(m0 + ar0) * K + akq;
    const float* aptr2 = aptr + (size_t)64 * K;
    const float* bptr  = Bw + (size_t)(n0 + ar0) * K + akq;

    float4 pa0 = *(const float4*)aptr;
    float4 pa1 = *(const float4*)aptr2;
    float4 pb  = *(const float4*)bptr;
    GEMM_STORE_SMEM();
    __syncthreads();

    float acc[8][4];
    #pragma unroll
    for (int i = 0; i < 8; i++)
        #pragma unroll
        for (int j = 0; j < 4; j++) acc[i][j] = 0.f;

    const int nk = K / BK;
    for (int kt = 0; kt < nk; kt++) {
        if (kt + 1 < nk) {
            aptr += BK; aptr2 += BK; bptr += BK;
            pa0 = *(const float4*)aptr;
            pa1 = *(const float4*)aptr2;
            pb  = *(const float4*)bptr;
        }
        #pragma unroll
        for (int kk = 0; kk < BK; kk++) {
            float4 a0 = *(const float4*)&As[kk][ty * 8];
            float4 a1 = *(const float4*)&As[kk][ty * 8 + 4];
            float4 b4 = *(const float4*)&Bs[kk][tx * 4];
            float am[8] = {a0.x, a0.y, a0.z, a0.w, a1.x, a1.y, a1.z, a1.w};
            float bm[4] = {b4.x, b4.y, b4.z, b4.w};
            #pragma unroll
            for (int i = 0; i < 8; i++)
                #pragma unroll
                for (int j = 0; j < 4; j++)
                    acc[i][j] += am[i] * bm[j];
        }
        __syncthreads();
        if (kt + 1 < nk) {
            GEMM_STORE_SMEM();
            __syncthreads();
        }
    }

    #pragma unroll
    for (int i = 0; i < 8; i++) {
        size_t idx = (size_t)(m0 + ty * 8 + i) * N + n0 + tx * 4;
        float vals[4] = {acc[i][0], acc[i][1], acc[i][2], acc[i][3]};
        if (EPI == 1) {
            #pragma unroll
            for (int j = 0; j < 4; j++)
                vals[j] = vals[j] * 0.5f * (1.f + erff(vals[j] * 0.70710678118654752f));
        } else if (EPI == 2) {
            float4 a1v = *(const float4*)(add1 + idx);
            float4 a2v = *(const float4*)(add2 + idx);
            vals[0] += a1v.x + a2v.x; vals[1] += a1v.y + a2v.y;
            vals[2] += a1v.z + a2v.z; vals[3] += a1v.w + a2v.w;
        }
        float4 o = {vals[0], vals[1], vals[2], vals[3]};
        *(float4*)(C + idx) = o;
    }
}

// ---------------- RoPE ------------------------------------------------------
__global__ void rope_q_kernel(float* __restrict__ q,
                              const float* __restrict__ ct, const float* __restrict__ st)
{
    int idx = blockIdx.x * blockDim.x + threadIdx.x;
    if (idx >= Mrows * NHh * 32) return;
    int d   = idx & 31;
    int hh  = (idx >> 5) % NHh;
    int row = idx / (32 * NHh);
    int s   = row & (Ss - 1);
    float* qp = q + (size_t)row * Hh + hh * HDd;
    float x1 = qp[d], x2 = qp[d + 32];
    float c1 = ct[s * HDd + d],      s1 = st[s * HDd + d];
    float c2 = ct[s * HDd + d + 32], s2 = st[s * HDd + d + 32];
    qp[d]      = x1 * c1 - x2 * s1;
    qp[d + 32] = x2 * c2 + x1 * s2;
}

__global__ void rope_k_kernel(float* __restrict__ k,
                              const float* __restrict__ ct, const float* __restrict__ st)
{
    int idx = blockIdx.x * blockDim.x + threadIdx.x;
    if (idx >= Mrows * 32) return;
    int d   = idx & 31;
    int row = idx >> 5;
    int s   = row & (Ss - 1);
    float* kp = k + (size_t)row * HDd;
    float x1 = kp[d], x2 = kp[d + 32];
    float c1 = ct[s * HDd + d],      s1 = st[s * HDd + d];
    float c2 = ct[s * HDd + d + 32], s2 = st[s * HDd + d + 32];
    kp[d]      = x1 * c1 - x2 * s1;
    kp[d + 32] = x2 * c2 + x1 * s2;
}

// ---------------- Flash attention (fp32, causal, MQA) -----------------------
// One CTA = (batch b, head h, 128 q-rows). Thread r owns q-row r entirely.
constexpr int QT = 128, KTile = 32;

__global__ void __launch_bounds__(128) attn_kernel(
    const float* __restrict__ q, const float* __restrict__ k,
    const float* __restrict__ v, float* __restrict__ ctx)
{
    __shared__ float ks[KTile][HDd];
    __shared__ float vs[KTile][HDd];
    __shared__ float ssb[QT][KTile + 1];

    int qt = blockIdx.x, h = blockIdx.y, b = blockIdx.z;
    int r  = threadIdx.x;
    int qi = qt * QT + r;                       // sequence position of this row

    float qreg[HDd];
    const float* qp = q + (size_t)(b * Ss + qi) * Hh + h * HDd;
    #pragma unroll
    for (int i = 0; i < 16; i++) {
        float4 t = *(const float4*)(qp + i * 4);
        qreg[i*4+0] = t.x * 0.125f; qreg[i*4+1] = t.y * 0.125f;   // 1/sqrt(64)
        qreg[i*4+2] = t.z * 0.125f; qreg[i*4+3] = t.w * 0.125f;
    }

    float m = -1e30f, l = 0.f;
    float O[HDd];
    #pragma unroll
    for (int d = 0; d < HDd; d++) O[d] = 0.f;
    float* srow = &ssb[r][0];

    const int nkb = 4 * qt + 4;                 // key blocks needed (causal)
    for (int kb = 0; kb < nkb; kb++) {
        __syncthreads();                        // protect ks/vs reuse
        const float4* kp = (const float4*)(k + (size_t)(b * Ss + kb * KTile) * HDd);
        const float4* vp = (const float4*)(v + (size_t)(b * Ss + kb * KTile) * HDd);
        for (int i = r; i < KTile * HDd / 4; i += QT) {
            ((float4*)ks)[i] = kp[i];
            ((float4*)vs)[i] = vp[i];
        }
        __syncthreads();

        bool edge = (kb >= 4 * qt);             // only last 4 blocks need masking
        float rowmax = m;
        for (int kk = 0; kk < KTile; kk++) {
            float s = 0.f;
            const float* kkp = &ks[kk][0];
            #pragma unroll
            for (int d4 = 0; d4 < 16; d4++) {
                float4 kv = *(const float4*)(kkp + d4 * 4);
                s += qreg[d4*4+0] * kv.x + qreg[d4*4+1] * kv.y
                   + qreg[d4*4+2] * kv.z + qreg[d4*4+3] * kv.w;
            }
            if (edge && (kb * KTile + kk > qi)) s = -1e30f;
            srow[kk] = s;
            rowmax = fmaxf(rowmax, s);
        }

        float corr = __expf(m - rowmax);
        l *= corr;
        #pragma unroll
        for (int d = 0; d < HDd; d++) O[d] *= corr;

        for (int kk = 0; kk < KTile; kk++) {
            float p = __expf(srow[kk] - rowmax);
            l += p;
            const float* vvp = &vs[kk][0];
            #pragma unroll
            for (int d4 = 0; d4 < 16; d4++) {
                float4 vv = *(const float4*)(vvp + d4 * 4);
                O[d4*4+0] += p * vv.x; O[d4*4+1] += p * vv.y;
                O[d4*4+2] += p * vv.z; O[d4*4+3] += p * vv.w;
            }
        }
        m = rowmax;
    }

    float inv = 1.f / l;
    float* op = ctx + (size_t)(b * Ss + qi) * Hh + h * HDd;
    #pragma unroll
    for (int i = 0; i < 16; i++) {
        float4 o = {O[i*4+0]*inv, O[i*4+1]*inv, O[i*4+2]*inv, O[i*4+3]*inv};
        *(float4*)(op + i * 4) = o;
    }
}

// ---------------- host: launch sequence -------------------------------------
extern "C" void kernel_launch(void* const* d_in, const int* in_sizes, int n_in,
                              void* d_out, int out_size)
{
    const float* hs   = (const float*)d_in[0];
    // d_in[1] attention_mask: unused by the reference math (all-ones; causal only)
    const float* ct   = (const float*)d_in[2];
    const float* st   = (const float*)d_in[3];
    const float* w1   = (const float*)d_in[4];
    const float* b1   = (const float*)d_in[5];
    const float* w2   = (const float*)d_in[6];
    const float* b2   = (const float*)d_in[7];
    const float* wq   = (const float*)d_in[8];
    const float* wk   = (const float*)d_in[9];
    const float* wv   = (const float*)d_in[10];
    const float* wd   = (const float*)d_in[11];
    const float* wh4h = (const float*)d_in[12];
    const float* w4hh = (const float*)d_in[13];
    float* out = (float*)d_out;

    float *p_ln, *p_q, *p_k, *p_v, *p_ctx, *p_att, *p_mlp;
    cudaGetSymbolAddress((void**)&p_ln,  g_ln);
    cudaGetSymbolAddress((void**)&p_q,   g_q);
    cudaGetSymbolAddress((void**)&p_k,   g_k);
    cudaGetSymbolAddress((void**)&p_v,   g_v);
    cudaGetSymbolAddress((void**)&p_ctx, g_ctx);
    cudaGetSymbolAddress((void**)&p_att, g_att);
    cudaGetSymbolAddress((void**)&p_mlp, g_mlp);

    // 1) LayerNorm
    ln_kernel<<<Mrows, 256>>>(hs, w1, b1, w2, b2, p_ln);

    // 2) Q/K/V projections
    gemm_nt<0><<<dim3(Hh / BN, Mrows / BM), 256>>>(p_ln, wq, p_q, Mrows, Hh, Hh, nullptr, nullptr);
    gemm_nt<0><<<dim3(1,       Mrows / BM), 256>>>(p_ln, wk, p_k, Mrows, 64, Hh, nullptr, nullptr);
    gemm_nt<0><<<dim3(1,       Mrows / BM), 256>>>(p_ln, wv, p_v, Mrows, 64, Hh, nullptr, nullptr);

    // 3) RoPE
    int nq = Mrows * NHh * 32;
    rope_q_kernel<<<(nq + 255) / 256, 256>>>(p_q, ct, st);
    int nk2 = Mrows * 32;
    rope_k_kernel<<<(nk2 + 255) / 256, 256>>>(p_k, ct, st);

    // 4) Causal flash attention (MQA: K/V shared across all 71 heads)
    attn_kernel<<<dim3(Ss / QT, NHh, Bb), 128>>>(p_q, p_k, p_v, p_ctx);

    // 5) Attention dense projection
    gemm_nt<0><<<dim3(Hh / BN, Mrows / BM), 256>>>(p_ctx, wd, p_att, Mrows, Hh, Hh, nullptr, nullptr);

    // 6) MLP up + exact gelu
    gemm_nt<1><<<dim3(H4 / BN, Mrows / BM), 256>>>(p_ln, wh4h, p_mlp, Mrows, H4, Hh, nullptr, nullptr);

    // 7) MLP down + attn_out + residual -> output
    gemm_nt<2><<<dim3(Hh / BN, Mrows / BM), 256>>>(p_mlp, w4hh, out, Mrows, Hh, H4, p_att, hs);
}

// round 8
// speedup vs baseline: 2.1673x; 2.1673x over previous
#include <cuda_runtime.h>
#include <cuda_bf16.h>
#include <math.h>
#include <stdint.h>

// Problem dims
#define Bb 2
#define Ss 1024
#define Hh 4544
#define NHh 71
#define HDd 64
#define H4 18176
#define Mrows 2048        // B*S
#define FRAC 4096

// ---------------- scratch (device globals) -----------------------------------
__device__ float g_ln [(size_t)Mrows * Hh];
__device__ float g_q  [(size_t)Mrows * Hh];
__device__ float g_k  [(size_t)Mrows * HDd];
__device__ float g_v  [(size_t)Mrows * HDd];
__device__ float g_ctx[(size_t)Mrows * Hh];
__device__ float g_att[(size_t)Mrows * Hh];
__device__ float g_mlp[(size_t)Mrows * H4];

// ---------------- helpers ----------------------------------------------------
__device__ __forceinline__ uint32_t smem_u32(const void* p) {
    uint32_t a;
    asm("{ .reg .u64 t; cvta.to.shared.u64 t, %1; cvt.u32.u64 %0, t; }" : "=r"(a) : "l"(p));
    return a;
}
__device__ __forceinline__ void ldsm4(uint32_t* r, uint32_t addr) {
    asm volatile("ldmatrix.sync.aligned.m8n8.x4.shared.b16 {%0,%1,%2,%3}, [%4];"
        : "=r"(r[0]), "=r"(r[1]), "=r"(r[2]), "=r"(r[3]) : "r"(addr));
}
__device__ __forceinline__ void mma16816(float* d, const uint32_t* a, const uint32_t* b) {
    asm volatile("mma.sync.aligned.m16n8k16.row.col.f32.bf16.bf16.f32 "
        "{%0,%1,%2,%3}, {%4,%5,%6,%7}, {%8,%9}, {%0,%1,%2,%3};"
        : "+f"(d[0]), "+f"(d[1]), "+f"(d[2]), "+f"(d[3])
        : "r"(a[0]), "r"(a[1]), "r"(a[2]), "r"(a[3]), "r"(b[0]), "r"(b[1]));
}
// fp32 -> bf16 hi/lo split, stored SW128-swizzled (8B-aligned boff).
__device__ __forceinline__ void cvst(float4 v, uint32_t baseHi, uint32_t baseLo, uint32_t boff) {
    __nv_bfloat162 h0 = __float22bfloat162_rn(make_float2(v.x, v.y));
    __nv_bfloat162 h1 = __float22bfloat162_rn(make_float2(v.z, v.w));
    float2 f0 = __bfloat1622float2(h0), f1 = __bfloat1622float2(h1);
    __nv_bfloat162 l0 = __float22bfloat162_rn(make_float2(v.x - f0.x, v.y - f0.y));
    __nv_bfloat162 l1 = __float22bfloat162_rn(make_float2(v.z - f1.x, v.w - f1.y));
    uint32_t sw = boff ^ ((boff >> 3) & 0x70);
    asm volatile("st.shared.v2.b32 [%0], {%1, %2};" ::
        "r"(baseHi + sw), "r"(*(uint32_t*)&h0), "r"(*(uint32_t*)&h1));
    asm volatile("st.shared.v2.b32 [%0], {%1, %2};" ::
        "r"(baseLo + sw), "r"(*(uint32_t*)&l0), "r"(*(uint32_t*)&l1));
}

// ---------------- warp-MMA GEMM: C[M,N] = A[M,K] * B[N,K]^T ------------------
// CTA: 128x64 tile, K-chunk 64, 8 warps (4m x 2n), warp tile 32x32.
// fp32-split-bf16 x3 HMMA accumulating in fp32 registers.
// EPI: 0 = plain, 1 = exact gelu, 2 = C + add1 + add2
template <int EPI>
__global__ void __launch_bounds__(256) gemm_mma(
    const float* __restrict__ A, const float* __restrict__ Bw,
    float* __restrict__ C, int N, int K,
    const float* __restrict__ add1, const float* __restrict__ add2)
{
    __shared__ __align__(128) uint8_t sm[49152];
    const uint32_t sb = smem_u32(sm);
    const uint32_t aH = sb, aL = sb + 16384, bH = sb + 32768, bL = sb + 40960;

    const int tid = threadIdx.x, lane = tid & 31, wid = tid >> 5;
    const int wm = wid & 3, wn = wid >> 2;
    const int m0 = blockIdx.x * 128, n0 = blockIdx.y * 64;
    const float4* A4 = (const float4*)A;
    const float4* B4 = (const float4*)Bw;
    const int kq = K >> 2;

    // ldmatrix lane address components
    const int rA_l   = lane & 15;
    const int kHalfA = lane >> 4;                       // 0/1 -> k chunk +0/+8
    const int rB_l   = (lane & 7) + ((lane >> 4) << 3); // n row within 16
    const int kHalfB = (lane >> 3) & 1;

    float acc[2][4][4];
    #pragma unroll
    for (int i = 0; i < 2; i++)
        #pragma unroll
        for (int j = 0; j < 4; j++)
            #pragma unroll
            for (int t = 0; t < 4; t++) acc[i][j][t] = 0.f;

    float4 pa[8], pb[4];

#define GLOAD(c) do {                                                           \
    int k0q = (c) * 16;                                                         \
    _Pragma("unroll")                                                           \
    for (int j = 0; j < 8; j++) {                                               \
        int idx = tid + j * 256;                                                \
        pa[j] = A4[(size_t)(m0 + (idx >> 4)) * kq + k0q + (idx & 15)];          \
    }                                                                           \
    _Pragma("unroll")                                                           \
    for (int j = 0; j < 4; j++) {                                               \
        int idx = tid + j * 256;                                                \
        pb[j] = B4[(size_t)(n0 + (idx >> 4)) * kq + k0q + (idx & 15)];          \
    }                                                                           \
} while (0)

#define SSTORE() do {                                                           \
    _Pragma("unroll")                                                           \
    for (int j = 0; j < 8; j++) {                                               \
        int idx = tid + j * 256;                                                \
        cvst(pa[j], aH, aL, (uint32_t)((idx >> 4) * 128 + (idx & 15) * 8));     \
    }                                                                           \
    _Pragma("unroll")                                                           \
    for (int j = 0; j < 4; j++) {                                               \
        int idx = tid + j * 256;                                                \
        cvst(pb[j], bH, bL, (uint32_t)((idx >> 4) * 128 + (idx & 15) * 8));     \
    }                                                                           \
} while (0)

    GLOAD(0);
    SSTORE();
    __syncthreads();

    const int NC = K >> 6;
    for (int i = 0; i < NC; i++) {
        if (i + 1 < NC) GLOAD(i + 1);

        #pragma unroll
        for (int ki = 0; ki < 4; ki++) {
            uint32_t ah[2][4], al[2][4], bh[2][4], bl[2][4];
            #pragma unroll
            for (int mi = 0; mi < 2; mi++) {
                int r = wm * 32 + mi * 16 + rA_l;
                uint32_t off = (uint32_t)r * 128
                             + (uint32_t)(((ki * 2 + kHalfA) ^ (r & 7)) << 4);
                ldsm4(ah[mi], aH + off);
                ldsm4(al[mi], aL + off);
            }
            #pragma unroll
            for (int nj = 0; nj < 2; nj++) {
                int r = wn * 32 + nj * 16 + rB_l;
                uint32_t off = (uint32_t)r * 128
                             + (uint32_t)(((ki * 2 + kHalfB) ^ (r & 7)) << 4);
                ldsm4(bh[nj], bH + off);
                ldsm4(bl[nj], bL + off);
            }
            #pragma unroll
            for (int mi = 0; mi < 2; mi++)
                #pragma unroll
                for (int nt = 0; nt < 4; nt++) {
                    const uint32_t* bhp = &bh[nt >> 1][(nt & 1) * 2];
                    const uint32_t* blp = &bl[nt >> 1][(nt & 1) * 2];
                    mma16816(acc[mi][nt], ah[mi], bhp);
                    mma16816(acc[mi][nt], ah[mi], blp);
                    mma16816(acc[mi][nt], al[mi], bhp);
                }
        }
        __syncthreads();
        if (i + 1 < NC) {
            SSTORE();
            __syncthreads();
        }
    }
#undef GLOAD
#undef SSTORE

    // Epilogue: c-frag lane mapping: c0,c1 -> (row lane/4, col 2(lane%4)+{0,1});
    // c2,c3 -> row+8.
    const int rw = lane >> 2, cw = (lane & 3) * 2;
    #pragma unroll
    for (int mi = 0; mi < 2; mi++)
        #pragma unroll
        for (int nt = 0; nt < 4; nt++) {
            float* d = acc[mi][nt];
            int row = m0 + wm * 32 + mi * 16 + rw;
            int col = n0 + wn * 32 + nt * 8 + cw;
            #pragma unroll
            for (int h = 0; h < 2; h++) {
                size_t idx = (size_t)(row + h * 8) * N + col;
                float v0 = d[h * 2 + 0], v1 = d[h * 2 + 1];
                if (EPI == 1) {
                    v0 = v0 * 0.5f * (1.f + erff(v0 * 0.70710678118654752f));
                    v1 = v1 * 0.5f * (1.f + erff(v1 * 0.70710678118654752f));
                } else if (EPI == 2) {
                    float2 a1 = *(const float2*)(add1 + idx);
                    float2 a2 = *(const float2*)(add2 + idx);
                    v0 += a1.x + a2.x;
                    v1 += a1.y + a2.y;
                }
                float2 o = {v0, v1};
                *(float2*)(C + idx) = o;
            }
        }
}

// ---------------- LayerNorm (fractured scale/bias) ---------------------------
__global__ void ln_kernel(const float* __restrict__ x,
                          const float* __restrict__ w1, const float* __restrict__ b1,
                          const float* __restrict__ w2, const float* __restrict__ b2,
                          float* __restrict__ out)
{
    int row = blockIdx.x;
    const float4* xr = (const float4*)(x + (size_t)row * Hh);
    float s = 0.f, sq = 0.f;
    for (int i = threadIdx.x; i < Hh / 4; i += blockDim.x) {
        float4 v = xr[i];
        s  += v.x + v.y + v.z + v.w;
        sq += v.x*v.x + v.y*v.y + v.z*v.z + v.w*v.w;
    }
    #pragma unroll
    for (int o = 16; o; o >>= 1) {
        s  += __shfl_xor_sync(0xffffffffu, s,  o);
        sq += __shfl_xor_sync(0xffffffffu, sq, o);
    }
    __shared__ float rs[8], rq[8], stats[2];
    int w = threadIdx.x >> 5;
    if ((threadIdx.x & 31) == 0) { rs[w] = s; rq[w] = sq; }
    __syncthreads();
    if (threadIdx.x == 0) {
        float ts = 0.f, tq = 0.f;
        #pragma unroll
        for (int i = 0; i < 8; i++) { ts += rs[i]; tq += rq[i]; }
        float mean = ts / (float)Hh;
        float var  = tq / (float)Hh - mean * mean;
        stats[0] = mean;
        stats[1] = rsqrtf(var + 1e-5f);
    }
    __syncthreads();
    float mean = stats[0], rstd = stats[1];
    float4* orow = (float4*)(out + (size_t)row * Hh);
    for (int i = threadIdx.x; i < Hh / 4; i += blockDim.x) {
        float4 v = xr[i];
        int c = i * 4;
        float vv[4] = {v.x, v.y, v.z, v.w};
        float ov[4];
        #pragma unroll
        for (int j = 0; j < 4; j++) {
            int cc = c + j;
            float ww, bb;
            if (cc < FRAC) { ww = w1[cc];        bb = b1[cc]; }
            else           { ww = w2[cc - FRAC]; bb = b2[cc - FRAC]; }
            ov[j] = (vv[j] - mean) * rstd * ww + bb;
        }
        float4 o = {ov[0], ov[1], ov[2], ov[3]};
        orow[i] = o;
    }
}

// ---------------- RoPE ------------------------------------------------------
__global__ void rope_q_kernel(float* __restrict__ q,
                              const float* __restrict__ ct, const float* __restrict__ st)
{
    int idx = blockIdx.x * blockDim.x + threadIdx.x;
    if (idx >= Mrows * NHh * 32) return;
    int d   = idx & 31;
    int hh  = (idx >> 5) % NHh;
    int row = idx / (32 * NHh);
    int s   = row & (Ss - 1);
    float* qp = q + (size_t)row * Hh + hh * HDd;
    float x1 = qp[d], x2 = qp[d + 32];
    float c1 = ct[s * HDd + d],      s1 = st[s * HDd + d];
    float c2 = ct[s * HDd + d + 32], s2 = st[s * HDd + d + 32];
    qp[d]      = x1 * c1 - x2 * s1;
    qp[d + 32] = x2 * c2 + x1 * s2;
}

__global__ void rope_k_kernel(float* __restrict__ k,
                              const float* __restrict__ ct, const float* __restrict__ st)
{
    int idx = blockIdx.x * blockDim.x + threadIdx.x;
    if (idx >= Mrows * 32) return;
    int d   = idx & 31;
    int row = idx >> 5;
    int s   = row & (Ss - 1);
    float* kp = k + (size_t)row * HDd;
    float x1 = kp[d], x2 = kp[d + 32];
    float c1 = ct[s * HDd + d],      s1 = st[s * HDd + d];
    float c2 = ct[s * HDd + d + 32], s2 = st[s * HDd + d + 32];
    kp[d]      = x1 * c1 - x2 * s1;
    kp[d + 32] = x2 * c2 + x1 * s2;
}

// ---------------- Flash attention (fp32, causal, MQA) -----------------------
constexpr int QT = 128, KTile = 32;

__global__ void __launch_bounds__(128) attn_kernel(
    const float* __restrict__ q, const float* __restrict__ k,
    const float* __restrict__ v, float* __restrict__ ctx)
{
    __shared__ float ks[KTile][HDd];
    __shared__ float vs[KTile][HDd];
    __shared__ float ssb[QT][KTile + 1];

    int qt = blockIdx.x, h = blockIdx.y, b = blockIdx.z;
    int r  = threadIdx.x;
    int qi = qt * QT + r;

    float qreg[HDd];
    const float* qp = q + (size_t)(b * Ss + qi) * Hh + h * HDd;
    #pragma unroll
    for (int i = 0; i < 16; i++) {
        float4 t = *(const float4*)(qp + i * 4);
        qreg[i*4+0] = t.x * 0.125f; qreg[i*4+1] = t.y * 0.125f;
        qreg[i*4+2] = t.z * 0.125f; qreg[i*4+3] = t.w * 0.125f;
    }

    float m = -1e30f, l = 0.f;
    float O[HDd];
    #pragma unroll
    for (int d = 0; d < HDd; d++) O[d] = 0.f;
    float* srow = &ssb[r][0];

    const int nkb = 4 * qt + 4;
    for (int kb = 0; kb < nkb; kb++) {
        __syncthreads();
        const float4* kp = (const float4*)(k + (size_t)(b * Ss + kb * KTile) * HDd);
        const float4* vp = (const float4*)(v + (size_t)(b * Ss + kb * KTile) * HDd);
        for (int i = r; i < KTile * HDd / 4; i += QT) {
            ((float4*)ks)[i] = kp[i];
            ((float4*)vs)[i] = vp[i];
        }
        __syncthreads();

        bool edge = (kb >= 4 * qt);
        float rowmax = m;
        for (int kk = 0; kk < KTile; kk++) {
            float s = 0.f;
            const float* kkp = &ks[kk][0];
            #pragma unroll
            for (int d4 = 0; d4 < 16; d4++) {
                float4 kv = *(const float4*)(kkp + d4 * 4);
                s += qreg[d4*4+0] * kv.x + qreg[d4*4+1] * kv.y
                   + qreg[d4*4+2] * kv.z + qreg[d4*4+3] * kv.w;
            }
            if (edge && (kb * KTile + kk > qi)) s = -1e30f;
            srow[kk] = s;
            rowmax = fmaxf(rowmax, s);
        }

        float corr = __expf(m - rowmax);
        l *= corr;
        #pragma unroll
        for (int d = 0; d < HDd; d++) O[d] *= corr;

        for (int kk = 0; kk < KTile; kk++) {
            float p = __expf(srow[kk] - rowmax);
            l += p;
            const float* vvp = &vs[kk][0];
            #pragma unroll
            for (int d4 = 0; d4 < 16; d4++) {
                float4 vv = *(const float4*)(vvp + d4 * 4);
                O[d4*4+0] += p * vv.x; O[d4*4+1] += p * vv.y;
                O[d4*4+2] += p * vv.z; O[d4*4+3] += p * vv.w;
            }
        }
        m = rowmax;
    }

    float inv = 1.f / l;
    float* op = ctx + (size_t)(b * Ss + qi) * Hh + h * HDd;
    #pragma unroll
    for (int i = 0; i < 16; i++) {
        float4 o = {O[i*4+0]*inv, O[i*4+1]*inv, O[i*4+2]*inv, O[i*4+3]*inv};
        *(float4*)(op + i * 4) = o;
    }
}

// ---------------- host: launch sequence -------------------------------------
extern "C" void kernel_launch(void* const* d_in, const int* in_sizes, int n_in,
                              void* d_out, int out_size)
{
    const float* hs   = (const float*)d_in[0];
    const float* ct   = (const float*)d_in[2];
    const float* st   = (const float*)d_in[3];
    const float* w1   = (const float*)d_in[4];
    const float* b1   = (const float*)d_in[5];
    const float* w2   = (const float*)d_in[6];
    const float* b2   = (const float*)d_in[7];
    const float* wq   = (const float*)d_in[8];
    const float* wk   = (const float*)d_in[9];
    const float* wv   = (const float*)d_in[10];
    const float* wd   = (const float*)d_in[11];
    const float* wh4h = (const float*)d_in[12];
    const float* w4hh = (const float*)d_in[13];
    float* out = (float*)d_out;

    float *p_ln, *p_q, *p_k, *p_v, *p_ctx, *p_att, *p_mlp;
    cudaGetSymbolAddress((void**)&p_ln,  g_ln);
    cudaGetSymbolAddress((void**)&p_q,   g_q);
    cudaGetSymbolAddress((void**)&p_k,   g_k);
    cudaGetSymbolAddress((void**)&p_v,   g_v);
    cudaGetSymbolAddress((void**)&p_ctx, g_ctx);
    cudaGetSymbolAddress((void**)&p_att, g_att);
    cudaGetSymbolAddress((void**)&p_mlp, g_mlp);

    // 1) LayerNorm
    ln_kernel<<<Mrows, 256>>>(hs, w1, b1, w2, b2, p_ln);

    // 2) Q/K/V projections (warp-MMA bf16-split)
    gemm_mma<0><<<dim3(16, 71), 256>>>(p_ln, wq, p_q, Hh, Hh, nullptr, nullptr);
    gemm_mma<0><<<dim3(16, 1),  256>>>(p_ln, wk, p_k, 64, Hh, nullptr, nullptr);
    gemm_mma<0><<<dim3(16, 1),  256>>>(p_ln, wv, p_v, 64, Hh, nullptr, nullptr);

    // 3) RoPE
    int nq = Mrows * NHh * 32;
    rope_q_kernel<<<(nq + 255) / 256, 256>>>(p_q, ct, st);
    int nk2 = Mrows * 32;
    rope_k_kernel<<<(nk2 + 255) / 256, 256>>>(p_k, ct, st);

    // 4) Causal flash attention (MQA)
    attn_kernel<<<dim3(Ss / QT, NHh, Bb), 128>>>(p_q, p_k, p_v, p_ctx);

    // 5) Attention dense projection
    gemm_mma<0><<<dim3(16, 71), 256>>>(p_ctx, wd, p_att, Hh, Hh, nullptr, nullptr);

    // 6) MLP up + exact gelu
    gemm_mma<1><<<dim3(16, 284), 256>>>(p_ln, wh4h, p_mlp, H4, Hh, nullptr, nullptr);

    // 7) MLP down + attn_out + residual -> output
    gemm_mma<2><<<dim3(16, 71), 256>>>(p_mlp, w4hh, out, Hh, H4, p_att, hs);
}

// round 10
// speedup vs baseline: 2.6226x; 1.2101x over previous
#include <cuda_runtime.h>
#include <cuda_bf16.h>
#include <math.h>
#include <stdint.h>

// Problem dims
#define Bb 2
#define Ss 1024
#define Hh 4544
#define NHh 71
#define HDd 64
#define H4 18176
#define Mrows 2048        // B*S
#define FRAC 4096
#define NQKV 4672         // 4544 + 64 + 64, = 73*64

typedef __nv_bfloat16 bf16;
typedef __nv_bfloat162 bf162;

// ---------------- scratch (device globals) -----------------------------------
__device__ bf16 g_ln_hi [(size_t)Mrows * Hh];
__device__ bf16 g_ln_lo [(size_t)Mrows * Hh];
__device__ float g_qkv  [(size_t)Mrows * NQKV];
__device__ bf16 g_ctx_hi[(size_t)Mrows * Hh];
__device__ bf16 g_ctx_lo[(size_t)Mrows * Hh];
__device__ float g_att  [(size_t)Mrows * Hh];
__device__ bf16 g_mlp_hi[(size_t)Mrows * H4];
__device__ bf16 g_mlp_lo[(size_t)Mrows * H4];
// split weights (rebuilt every call; deterministic)
__device__ bf16 g_wqkv_hi[(size_t)NQKV * Hh];
__device__ bf16 g_wqkv_lo[(size_t)NQKV * Hh];
__device__ bf16 g_wd_hi  [(size_t)Hh * Hh];
__device__ bf16 g_wd_lo  [(size_t)Hh * Hh];
__device__ bf16 g_w1_hi  [(size_t)H4 * Hh];
__device__ bf16 g_w1_lo  [(size_t)H4 * Hh];
__device__ bf16 g_w2_hi  [(size_t)Hh * H4];
__device__ bf16 g_w2_lo  [(size_t)Hh * H4];

// ---------------- helpers ----------------------------------------------------
__device__ __forceinline__ uint32_t smem_u32(const void* p) {
    uint32_t a;
    asm("{ .reg .u64 t; cvta.to.shared.u64 t, %1; cvt.u32.u64 %0, t; }" : "=r"(a) : "l"(p));
    return a;
}
__device__ __forceinline__ void ldsm4(uint32_t* r, uint32_t addr) {
    asm volatile("ldmatrix.sync.aligned.m8n8.x4.shared.b16 {%0,%1,%2,%3}, [%4];"
        : "=r"(r[0]), "=r"(r[1]), "=r"(r[2]), "=r"(r[3]) : "r"(addr));
}
__device__ __forceinline__ void mma16816(float* d, const uint32_t* a, const uint32_t* b) {
    asm volatile("mma.sync.aligned.m16n8k16.row.col.f32.bf16.bf16.f32 "
        "{%0,%1,%2,%3}, {%4,%5,%6,%7}, {%8,%9}, {%0,%1,%2,%3};"
        : "+f"(d[0]), "+f"(d[1]), "+f"(d[2]), "+f"(d[3])
        : "r"(a[0]), "r"(a[1]), "r"(a[2]), "r"(a[3]), "r"(b[0]), "r"(b[1]));
}
__device__ __forceinline__ void cpasync16(uint32_t dst, const void* src) {
    asm volatile("cp.async.cg.shared.global [%0], [%1], 16;" :: "r"(dst), "l"(src));
}
// split a pair of fp32 into hi/lo bf162
__device__ __forceinline__ void split2(float x, float y, bf162& h, bf162& l) {
    h = __float22bfloat162_rn(make_float2(x, y));
    float2 f = __bfloat1622float2(h);
    l = __float22bfloat162_rn(make_float2(x - f.x, y - f.y));
}

// ---------------- weight split: fp32 -> bf16 hi/lo planes --------------------
__global__ void cvt_split(const float* __restrict__ x, bf16* __restrict__ hi,
                          bf16* __restrict__ lo, size_t n4)
{
    size_t i = (size_t)blockIdx.x * blockDim.x + threadIdx.x;
    if (i >= n4) return;
    float4 v = ((const float4*)x)[i];
    bf162 h0, l0, h1, l1;
    split2(v.x, v.y, h0, l0);
    split2(v.z, v.w, h1, l1);
    ((bf162*)hi)[i * 2]     = h0;
    ((bf162*)hi)[i * 2 + 1] = h1;
    ((bf162*)lo)[i * 2]     = l0;
    ((bf162*)lo)[i * 2 + 1] = l1;
}

// ---------------- cp.async warp-MMA GEMM: C[M,N] = A[M,K]*B[N,K]^T ----------
// BM=256, BN in {64,128}, K-chunk 64, 512 threads (16 warps, 8m x 2n),
// operands pre-split bf16 hi/lo planes; 3-term HMMA, fp32 accum.
// EPI: 0 = fp32 C, 1 = gelu -> split to Chi/Clo, 2 = C + add1 + add2 (fp32)
template <int EPI, int BN>
__global__ void __launch_bounds__(512, 1) gemm_mma(
    const bf16* __restrict__ Ahi, const bf16* __restrict__ Alo,
    const bf16* __restrict__ Bhi, const bf16* __restrict__ Blo,
    float* __restrict__ C, bf16* __restrict__ Chi, bf16* __restrict__ Clo,
    int N, int K,
    const float* __restrict__ add1, const float* __restrict__ add2)
{
    constexpr int BM  = 256;
    constexpr int APL = BM * 128;           // bytes per A plane per stage
    constexpr int BPL = BN * 128;
    constexpr int STAGE = 2 * APL + 2 * BPL;
    constexpr int NF = BN / 32;             // B n16-frags per warp (2 or 4)
    extern __shared__ uint8_t smem[];
    const uint32_t sb = smem_u32(smem);

    const int tid = threadIdx.x, lane = tid & 31, wid = tid >> 5;
    const int wm = wid & 7, wn = wid >> 3;
    const int m0 = blockIdx.x * BM, n0 = blockIdx.y * BN;

    const int rA_l   = lane & 15;
    const int kHalfA = lane >> 4;
    const int rB_l   = (lane & 7) + ((lane >> 4) << 3);
    const int kHalfB = (lane >> 3) & 1;

    float acc[2][2 * NF][4];
    #pragma unroll
    for (int i = 0; i < 2; i++)
        #pragma unroll
        for (int j = 0; j < 2 * NF; j++)
            #pragma unroll
            for (int t = 0; t < 4; t++) acc[i][j][t] = 0.f;

#define ISSUE(c) do {                                                           \
    int k0 = (c) * 64;                                                          \
    uint32_t st_ = sb + ((c) & 1) * STAGE;                                      \
    _Pragma("unroll")                                                           \
    for (int p = 0; p < 2; p++) {                                               \
        const bf16* src = p ? Alo : Ahi;                                        \
        uint32_t base = st_ + p * APL;                                          \
        _Pragma("unroll")                                                       \
        for (int j = 0; j < 4; j++) {                                           \
            int g = tid + j * 512;                                              \
            int row = g >> 3, gk = g & 7;                                       \
            uint32_t dst = base + row * 128 + (uint32_t)((gk ^ (row & 7)) << 4);\
            cpasync16(dst, src + (size_t)(m0 + row) * K + k0 + gk * 8);         \
        }                                                                       \
    }                                                                           \
    _Pragma("unroll")                                                           \
    for (int p = 0; p < 2; p++) {                                               \
        const bf16* src = p ? Blo : Bhi;                                        \
        uint32_t base = st_ + 2 * APL + p * BPL;                                \
        _Pragma("unroll")                                                       \
        for (int j = 0; j < BN / 64; j++) {                                     \
            int g = tid + j * 512;                                              \
            int row = g >> 3, gk = g & 7;                                       \
            uint32_t dst = base + row * 128 + (uint32_t)((gk ^ (row & 7)) << 4);\
            cpasync16(dst, src + (size_t)(n0 + row) * K + k0 + gk * 8);         \
        }                                                                       \
    }                                                                           \
    asm volatile("cp.async.commit_group;" ::: "memory");                        \
} while (0)

    ISSUE(0);
    ISSUE(1);

    const int NC = K >> 6;
    for (int i = 0; i < NC; i++) {
        asm volatile("cp.async.wait_group 1;" ::: "memory");
        __syncthreads();
        const uint32_t st_ = sb + (i & 1) * STAGE;
        const uint32_t aH = st_, aL = st_ + APL;
        const uint32_t bH = st_ + 2 * APL, bL = bH + BPL;

        #pragma unroll
        for (int ki = 0; ki < 4; ki++) {
            uint32_t ah[2][4], al[2][4];
            #pragma unroll
            for (int mi = 0; mi < 2; mi++) {
                int r = wm * 32 + mi * 16 + rA_l;
                uint32_t off = (uint32_t)r * 128
                             + (uint32_t)(((ki * 2 + kHalfA) ^ (r & 7)) << 4);
                ldsm4(ah[mi], aH + off);
                ldsm4(al[mi], aL + off);
            }
            #pragma unroll
            for (int nj = 0; nj < NF; nj++) {
                uint32_t bh[4], bl[4];
                int r = wn * (BN / 2) + nj * 16 + rB_l;
                uint32_t off = (uint32_t)r * 128
                             + (uint32_t)(((ki * 2 + kHalfB) ^ (r & 7)) << 4);
                ldsm4(bh, bH + off);
                ldsm4(bl, bL + off);
                #pragma unroll
                for (int mi = 0; mi < 2; mi++)
                    #pragma unroll
                    for (int hf = 0; hf < 2; hf++) {
                        mma16816(acc[mi][nj * 2 + hf], ah[mi], &bh[hf * 2]);
                        mma16816(acc[mi][nj * 2 + hf], ah[mi], &bl[hf * 2]);
                        mma16816(acc[mi][nj * 2 + hf], al[mi], &bh[hf * 2]);
                    }
            }
        }
        __syncthreads();
        if (i + 2 < NC) ISSUE(i + 2);
        else asm volatile("cp.async.commit_group;" ::: "memory");
    }
#undef ISSUE

    // Epilogue. c-frag map: c0,c1 -> (row lane/4, col 2(lane%4)+{0,1}); c2,c3 -> row+8.
    const int rw = lane >> 2, cw = (lane & 3) * 2;
    #pragma unroll
    for (int mi = 0; mi < 2; mi++)
        #pragma unroll
        for (int nt = 0; nt < 2 * NF; nt++) {
            float* d = acc[mi][nt];
            int row = m0 + wm * 32 + mi * 16 + rw;
            int col = n0 + wn * (BN / 2) + nt * 8 + cw;
            #pragma unroll
            for (int h = 0; h < 2; h++) {
                size_t idx = (size_t)(row + h * 8) * N + col;
                float v0 = d[h * 2 + 0], v1 = d[h * 2 + 1];
                if (EPI == 1) {
                    v0 = v0 * 0.5f * (1.f + erff(v0 * 0.70710678118654752f));
                    v1 = v1 * 0.5f * (1.f + erff(v1 * 0.70710678118654752f));
                    bf162 hh, ll;
                    split2(v0, v1, hh, ll);
                    *(bf162*)(Chi + idx) = hh;
                    *(bf162*)(Clo + idx) = ll;
                } else {
                    if (EPI == 2) {
                        float2 a1 = *(const float2*)(add1 + idx);
                        float2 a2 = *(const float2*)(add2 + idx);
                        v0 += a1.x + a2.x;
                        v1 += a1.y + a2.y;
                    }
                    float2 o = {v0, v1};
                    *(float2*)(C + idx) = o;
                }
            }
        }
}

// ---------------- LayerNorm (fractured) -> split bf16 hi/lo ------------------
__global__ void ln_kernel(const float* __restrict__ x,
                          const float* __restrict__ w1, const float* __restrict__ b1,
                          const float* __restrict__ w2, const float* __restrict__ b2,
                          bf16* __restrict__ ohi, bf16* __restrict__ olo)
{
    int row = blockIdx.x;
    const float4* xr = (const float4*)(x + (size_t)row * Hh);
    float s = 0.f, sq = 0.f;
    for (int i = threadIdx.x; i < Hh / 4; i += blockDim.x) {
        float4 v = xr[i];
        s  += v.x + v.y + v.z + v.w;
        sq += v.x*v.x + v.y*v.y + v.z*v.z + v.w*v.w;
    }
    #pragma unroll
    for (int o = 16; o; o >>= 1) {
        s  += __shfl_xor_sync(0xffffffffu, s,  o);
        sq += __shfl_xor_sync(0xffffffffu, sq, o);
    }
    __shared__ float rs[8], rq[8], stats[2];
    int w = threadIdx.x >> 5;
    if ((threadIdx.x & 31) == 0) { rs[w] = s; rq[w] = sq; }
    __syncthreads();
    if (threadIdx.x == 0) {
        float ts = 0.f, tq = 0.f;
        #pragma unroll
        for (int i = 0; i < 8; i++) { ts += rs[i]; tq += rq[i]; }
        float mean = ts / (float)Hh;
        float var  = tq / (float)Hh - mean * mean;
        stats[0] = mean;
        stats[1] = rsqrtf(var + 1e-5f);
    }
    __syncthreads();
    float mean = stats[0], rstd = stats[1];
    bf162* hr = (bf162*)(ohi + (size_t)row * Hh);
    bf162* lr = (bf162*)(olo + (size_t)row * Hh);
    for (int i = threadIdx.x; i < Hh / 4; i += blockDim.x) {
        float4 v = xr[i];
        int c = i * 4;
        float vv[4] = {v.x, v.y, v.z, v.w};
        float ov[4];
        #pragma unroll
        for (int j = 0; j < 4; j++) {
            int cc = c + j;
            float ww, bb;
            if (cc < FRAC) { ww = w1[cc];        bb = b1[cc]; }
            else           { ww = w2[cc - FRAC]; bb = b2[cc - FRAC]; }
            ov[j] = (vv[j] - mean) * rstd * ww + bb;
        }
        bf162 h0, l0, h1, l1;
        split2(ov[0], ov[1], h0, l0);
        split2(ov[2], ov[3], h1, l1);
        hr[i * 2] = h0; hr[i * 2 + 1] = h1;
        lr[i * 2] = l0; lr[i * 2 + 1] = l1;
    }
}

// ---------------- fused RoPE over q heads (0..70) + k (slot 71) --------------
__global__ void rope_kernel(float* __restrict__ qkv,
                            const float* __restrict__ ct, const float* __restrict__ st)
{
    int idx = blockIdx.x * blockDim.x + threadIdx.x;
    if (idx >= Mrows * 72 * 32) return;
    int d   = idx & 31;
    int hh  = (idx >> 5) % 72;
    int row = idx / (32 * 72);
    int s   = row & (Ss - 1);
    float* p = qkv + (size_t)row * NQKV + (hh < 71 ? hh * 64 : 4544);
    float x1 = p[d], x2 = p[d + 32];
    float c1 = ct[s * HDd + d],      s1 = st[s * HDd + d];
    float c2 = ct[s * HDd + d + 32], s2 = st[s * HDd + d + 32];
    p[d]      = x1 * c1 - x2 * s1;
    p[d + 32] = x2 * c2 + x1 * s2;
}

// ---------------- Flash attention (fp32, causal, MQA) -----------------------
// Reads packed qkv (stride NQKV); writes ctx split hi/lo bf16.
constexpr int QT = 128, KTile = 32;

__global__ void __launch_bounds__(128) attn_kernel(
    const float* __restrict__ qkv, bf16* __restrict__ chi, bf16* __restrict__ clo)
{
    __shared__ float ks[KTile][HDd];
    __shared__ float vs[KTile][HDd];
    __shared__ float ssb[QT][KTile + 1];

    int qt = blockIdx.x, h = blockIdx.y, b = blockIdx.z;
    int r  = threadIdx.x;
    int qi = qt * QT + r;

    float qreg[HDd];
    const float* qp = qkv + (size_t)(b * Ss + qi) * NQKV + h * HDd;
    #pragma unroll
    for (int i = 0; i < 16; i++) {
        float4 t = *(const float4*)(qp + i * 4);
        qreg[i*4+0] = t.x * 0.125f; qreg[i*4+1] = t.y * 0.125f;
        qreg[i*4+2] = t.z * 0.125f; qreg[i*4+3] = t.w * 0.125f;
    }

    float m = -1e30f, l = 0.f;
    float O[HDd];
    #pragma unroll
    for (int d = 0; d < HDd; d++) O[d] = 0.f;
    float* srow = &ssb[r][0];

    const int nkb = 4 * qt + 4;
    for (int kb = 0; kb < nkb; kb++) {
        __syncthreads();
        const float* kb0 = qkv + (size_t)(b * Ss + kb * KTile) * NQKV + 4544;
        for (int i = r; i < KTile * HDd / 4; i += QT) {
            int rr = i >> 4, c = i & 15;
            const float* base = kb0 + (size_t)rr * NQKV + c * 4;
            ((float4*)ks)[i] = *(const float4*)base;
            ((float4*)vs)[i] = *(const float4*)(base + 64);
        }
        __syncthreads();

        bool edge = (kb >= 4 * qt);
        float rowmax = m;
        for (int kk = 0; kk < KTile; kk++) {
            float s = 0.f;
            const float* kkp = &ks[kk][0];
            #pragma unroll
            for (int d4 = 0; d4 < 16; d4++) {
                float4 kv = *(const float4*)(kkp + d4 * 4);
                s += qreg[d4*4+0] * kv.x + qreg[d4*4+1] * kv.y
                   + qreg[d4*4+2] * kv.z + qreg[d4*4+3] * kv.w;
            }
            if (edge && (kb * KTile + kk > qi)) s = -1e30f;
            srow[kk] = s;
            rowmax = fmaxf(rowmax, s);
        }

        float corr = __expf(m - rowmax);
        l *= corr;
        #pragma unroll
        for (int d = 0; d < HDd; d++) O[d] *= corr;

        for (int kk = 0; kk < KTile; kk++) {
            float p = __expf(srow[kk] - rowmax);
            l += p;
            const float* vvp = &vs[kk][0];
            #pragma unroll
            for (int d4 = 0; d4 < 16; d4++) {
                float4 vv = *(const float4*)(vvp + d4 * 4);
                O[d4*4+0] += p * vv.x; O[d4*4+1] += p * vv.y;
                O[d4*4+2] += p * vv.z; O[d4*4+3] += p * vv.w;
            }
        }
        m = rowmax;
    }

    float inv = 1.f / l;
    size_t base = (size_t)(b * Ss + qi) * Hh + h * HDd;
    #pragma unroll
    for (int i = 0; i < 16; i++) {
        float o0 = O[i*4+0]*inv, o1 = O[i*4+1]*inv;
        float o2 = O[i*4+2]*inv, o3 = O[i*4+3]*inv;
        bf162 h0, l0, h1, l1;
        split2(o0, o1, h0, l0);
        split2(o2, o3, h1, l1);
        *(bf162*)(chi + base + i * 4)     = h0;
        *(bf162*)(chi + base + i * 4 + 2) = h1;
        *(bf162*)(clo + base + i * 4)     = l0;
        *(bf162*)(clo + base + i * 4 + 2) = l1;
    }
}

// ---------------- host: launch sequence -------------------------------------
extern "C" void kernel_launch(void* const* d_in, const int* in_sizes, int n_in,
                              void* d_out, int out_size)
{
    const float* hs   = (const float*)d_in[0];
    const float* ct   = (const float*)d_in[2];
    const float* st   = (const float*)d_in[3];
    const float* w1   = (const float*)d_in[4];
    const float* b1   = (const float*)d_in[5];
    const float* w2   = (const float*)d_in[6];
    const float* b2   = (const float*)d_in[7];
    const float* wq   = (const float*)d_in[8];
    const float* wk   = (const float*)d_in[9];
    const float* wv   = (const float*)d_in[10];
    const float* wd   = (const float*)d_in[11];
    const float* wh4h = (const float*)d_in[12];
    const float* w4hh = (const float*)d_in[13];
    float* out = (float*)d_out;

    bf16 *p_ln_hi, *p_ln_lo, *p_ctx_hi, *p_ctx_lo, *p_mlp_hi, *p_mlp_lo;
    bf16 *p_wqkv_hi, *p_wqkv_lo, *p_wd_hi, *p_wd_lo, *p_w1_hi, *p_w1_lo, *p_w2_hi, *p_w2_lo;
    float *p_qkv, *p_att;
    cudaGetSymbolAddress((void**)&p_ln_hi,  g_ln_hi);
    cudaGetSymbolAddress((void**)&p_ln_lo,  g_ln_lo);
    cudaGetSymbolAddress((void**)&p_qkv,    g_qkv);
    cudaGetSymbolAddress((void**)&p_ctx_hi, g_ctx_hi);
    cudaGetSymbolAddress((void**)&p_ctx_lo, g_ctx_lo);
    cudaGetSymbolAddress((void**)&p_att,    g_att);
    cudaGetSymbolAddress((void**)&p_mlp_hi, g_mlp_hi);
    cudaGetSymbolAddress((void**)&p_mlp_lo, g_mlp_lo);
    cudaGetSymbolAddress((void**)&p_wqkv_hi, g_wqkv_hi);
    cudaGetSymbolAddress((void**)&p_wqkv_lo, g_wqkv_lo);
    cudaGetSymbolAddress((void**)&p_wd_hi,  g_wd_hi);
    cudaGetSymbolAddress((void**)&p_wd_lo,  g_wd_lo);
    cudaGetSymbolAddress((void**)&p_w1_hi,  g_w1_hi);
    cudaGetSymbolAddress((void**)&p_w1_lo,  g_w1_lo);
    cudaGetSymbolAddress((void**)&p_w2_hi,  g_w2_hi);
    cudaGetSymbolAddress((void**)&p_w2_lo,  g_w2_lo);

    constexpr int SMEM64  = 2 * (2 * 256 * 128 + 2 * 64 * 128);   // 163840
    constexpr int SMEM128 = 2 * (2 * 256 * 128 + 2 * 128 * 128);  // 196608
    cudaFuncSetAttribute(gemm_mma<0, 64>,  cudaFuncAttributeMaxDynamicSharedMemorySize, SMEM64);
    cudaFuncSetAttribute(gemm_mma<1, 128>, cudaFuncAttributeMaxDynamicSharedMemorySize, SMEM128);
    cudaFuncSetAttribute(gemm_mma<2, 64>,  cudaFuncAttributeMaxDynamicSharedMemorySize, SMEM64);

    // 0) split weights into bf16 hi/lo planes (qkv concatenated: q rows, k, v)
    auto nblk = [](size_t n4) { return (int)((n4 + 255) / 256); };
    size_t nq4 = (size_t)Hh * Hh / 4, nk4 = (size_t)HDd * Hh / 4;
    cvt_split<<<nblk(nq4), 256>>>(wq, p_wqkv_hi, p_wqkv_lo, nq4);
    cvt_split<<<nblk(nk4), 256>>>(wk, p_wqkv_hi + (size_t)Hh * Hh,
                                      p_wqkv_lo + (size_t)Hh * Hh, nk4);
    cvt_split<<<nblk(nk4), 256>>>(wv, p_wqkv_hi + (size_t)(Hh + 64) * Hh,
                                      p_wqkv_lo + (size_t)(Hh + 64) * Hh, nk4);
    size_t nd4 = (size_t)Hh * Hh / 4, n14 = (size_t)H4 * Hh / 4;
    cvt_split<<<nblk(nd4), 256>>>(wd,   p_wd_hi, p_wd_lo, nd4);
    cvt_split<<<nblk(n14), 256>>>(wh4h, p_w1_hi, p_w1_lo, n14);
    cvt_split<<<nblk(n14), 256>>>(w4hh, p_w2_hi, p_w2_lo, n14);

    // 1) LayerNorm -> split hi/lo
    ln_kernel<<<Mrows, 256>>>(hs, b1 ? w1 : w1, b1, w2, b2, p_ln_hi, p_ln_lo);

    // 2) fused QKV projection (N = 4672)
    gemm_mma<0, 64><<<dim3(8, 73), 512, SMEM64>>>(
        p_ln_hi, p_ln_lo, p_wqkv_hi, p_wqkv_lo,
        p_qkv, nullptr, nullptr, NQKV, Hh, nullptr, nullptr);

    // 3) RoPE (q heads + k)
    int nr = Mrows * 72 * 32;
    rope_kernel<<<(nr + 255) / 256, 256>>>(p_qkv, ct, st);

    // 4) causal flash attention (MQA) -> ctx split hi/lo
    attn_kernel<<<dim3(Ss / QT, NHh, Bb), 128>>>(p_qkv, p_ctx_hi, p_ctx_lo);

    // 5) attention dense projection
    gemm_mma<0, 64><<<dim3(8, 71), 512, SMEM64>>>(
        p_ctx_hi, p_ctx_lo, p_wd_hi, p_wd_lo,
        p_att, nullptr, nullptr, Hh, Hh, nullptr, nullptr);

    // 6) MLP up + exact gelu -> split hi/lo
    gemm_mma<1, 128><<<dim3(8, 142), 512, SMEM128>>>(
        p_ln_hi, p_ln_lo, p_w1_hi, p_w1_lo,
        nullptr, p_mlp_hi, p_mlp_lo, H4, Hh, nullptr, nullptr);

    // 7) MLP down + attn_out + residual -> output
    gemm_mma<2, 64><<<dim3(8, 71), 512, SMEM64>>>(
        p_mlp_hi, p_mlp_lo, p_w2_hi, p_w2_lo,
        out, nullptr, nullptr, Hh, H4, p_att, hs);
}